// round 15
// baseline (speedup 1.0000x reference)
#include <cuda_runtime.h>
#include <cstdint>

#define NNODES 100000
#define EMAX   1700000
#define HID    64
#define FIN    128
#define NCLS   40

// ------------------------------ device scratch ------------------------------
__device__ float g_bufA[NNODES * HID];
__device__ float g_bufB[NNODES * HID];
__device__ float g_as[NNODES];
__device__ float g_ad[NNODES];
__device__ int   g_deg[NNODES];
__device__ int   g_off[NNODES + 1];
__device__ int   g_pos[NNODES];
__device__ int   g_csr_src[EMAX];
__device__ int   g_esrc[EMAX];
__device__ int   g_edst[EMAX];
__device__ int   g_bsum[128];
__device__ volatile int g_flag[128];
__device__ int   g_idx32;
__device__ unsigned g_mxu[4];
// collapsed weights: [0:64) Wc0@attS0, [64:128) Wc0@attD0,
//                    [128:192) Wc1@attS1, [192:256) Wc1@attD1
__device__ float g_wvec[256];
__device__ float g_Wfin[HID * NCLS];   // Wc1 @ W2
__device__ float g_bfin[NCLS];         // bias1 @ W2 + b2

__device__ __forceinline__ float lrelu(float x) { return x > 0.f ? x : 0.2f * x; }

__device__ __forceinline__ unsigned fenc(float f) {
    unsigned u = __float_as_uint(f);
    return (u & 0x80000000u) ? ~u : (u | 0x80000000u);
}
__device__ __forceinline__ float fdec(unsigned k) {
    return (k & 0x80000000u) ? __uint_as_float(k & 0x7fffffffu)
                             : __uint_as_float(~k);
}

#define FMA2(d, a, b) asm("fma.rn.f32x2 %0, %1, %2, %0;" : "+l"(d) : "l"(a), "l"(b))
#define DUP2(d, f)    asm("mov.b64 %0, {%1, %1};" : "=l"(d) : "f"(f))

__device__ __forceinline__ float f2lo(unsigned long long v) {
    return __uint_as_float((unsigned)(v & 0xffffffffu));
}
__device__ __forceinline__ float f2hi(unsigned long long v) {
    return __uint_as_float((unsigned)(v >> 32));
}

// ------------- init (side stream): zero deg/flags, detect dtype -------------
__global__ void k_init(const int* __restrict__ w, int nwords) {
    __shared__ int nz;
    int i = blockIdx.x * blockDim.x + threadIdx.x;
    if (i < NNODES) g_deg[i] = 0;
    if (i < 128) g_flag[i] = 0;
    if (blockIdx.x == 0) {
        if (threadIdx.x == 0) nz = 0;
        __syncthreads();
        int n = nwords < 4096 ? nwords : 4096;
        int found = 0;
        for (int j = 2 * threadIdx.x + 1; j < n; j += 2 * blockDim.x)
            if (w[j] != 0) found = 1;
        if (found) atomicExch(&nz, 1);
        __syncthreads();
        if (threadIdx.x == 0) g_idx32 = nz;
    }
}

// ------------- precompute (main stream, parallel): collapsed weights --------
__global__ void k_pre(const float* __restrict__ Wc0, const float* __restrict__ aS0,
                      const float* __restrict__ aD0,
                      const float* __restrict__ Wc1, const float* __restrict__ aS1,
                      const float* __restrict__ aD1,
                      const float* __restrict__ W2, const float* __restrict__ bi1,
                      const float* __restrict__ b2) {
    int t = threadIdx.x;
    if (blockIdx.x == 0) {
        if (t < 4) g_mxu[t] = 0u;
        if (t >= 128) return;
        if (t < 64) {
            float s0 = 0.f, d0 = 0.f, s1 = 0.f, d1 = 0.f;
#pragma unroll 8
            for (int k = 0; k < 64; k++) {
                float w0 = Wc0[t * 64 + k];
                float w1 = Wc1[t * 64 + k];
                s0 += w0 * aS0[k]; d0 += w0 * aD0[k];
                s1 += w1 * aS1[k]; d1 += w1 * aD1[k];
            }
            g_wvec[t] = s0; g_wvec[64 + t] = d0;
            g_wvec[128 + t] = s1; g_wvec[192 + t] = d1;
        } else if (t - 64 < NCLS) {
            int j = t - 64;
            float s = b2[j];
#pragma unroll 8
            for (int k = 0; k < 64; k++) s += bi1[k] * W2[k * NCLS + j];
            g_bfin[j] = s;
        }
    } else {
        int idx = (blockIdx.x - 1) * 128 + t;
        if (idx < HID * NCLS) {
            int i = idx / NCLS, j = idx % NCLS;
            float s = 0.f;
#pragma unroll 8
            for (int k = 0; k < 64; k++) s += Wc1[i * 64 + k] * W2[k * NCLS + j];
            g_Wfin[idx] = s;
        }
    }
}

__global__ void k_convert_hist(const void* __restrict__ ei, int E) {
    int e = blockIdx.x * blockDim.x + threadIdx.x;
    if (e >= E) return;
    int s, d;
    if (g_idx32) {
        const int* p = (const int*)ei;
        s = p[e]; d = p[E + e];
    } else {
        const long long* p = (const long long*)ei;
        s = (int)p[e]; d = (int)p[E + e];
    }
    g_esrc[e] = s;
    g_edst[e] = d;
    atomicAdd(&g_deg[d], 1);
}

// ---------------- single-kernel scan (all 98 blocks resident) ---------------
__global__ void k_scan() {
    __shared__ int sh[1024];
    __shared__ int s_off;
    int bid = blockIdx.x;
    int tid = threadIdx.x;
    int i = bid * 1024 + tid;
    int v = (i < NNODES) ? g_deg[i] : 0;
    sh[tid] = v;
    if (tid == 0) s_off = 0;
    __syncthreads();
    for (int o = 1; o < 1024; o <<= 1) {
        int t = 0;
        if (tid >= o) t = sh[tid - o];
        __syncthreads();
        sh[tid] += t;
        __syncthreads();
    }
    if (tid == 1023) {
        g_bsum[bid] = sh[1023];
        __threadfence();
        g_flag[bid] = 1;
    }
    if (tid < bid) {
        while (g_flag[tid] == 0) { }
        atomicAdd(&s_off, g_bsum[tid]);
    }
    __syncthreads();
    if (i < NNODES) {
        int incl = sh[tid] + s_off;
        int excl = incl - v;
        g_off[i] = excl;
        g_pos[i] = excl;
        if (i == NNODES - 1) g_off[NNODES] = incl;
    }
}

__global__ void k_scatter(int E) {
    int e = blockIdx.x * blockDim.x + threadIdx.x;
    if (e < E) {
        int d = g_edst[e];
        int p = atomicAdd(&g_pos[d], 1);
        g_csr_src[p] = g_esrc[e];
    }
}

// ------------------------------ GEMM (FFMA2, 8x8) ---------------------------
// 128-thread CTA, 128-row tile, 8 rows x 8 cols per thread (R10 config).
// sXT: transposed X tile [K][128], XOR-4 swizzle keyed on (k>>2)&7.
template <int K, int NC, bool ATT, bool BIAS, bool RELU, bool LSM>
__global__ void k_gemm(const float* __restrict__ X, const float* __restrict__ Wg,
                       const float* __restrict__ bias,
                       const float* __restrict__ attS, const float* __restrict__ attD,
                       float* __restrict__ out, int slot) {
    extern __shared__ float smem[];
    float* sW  = smem;               // [K][64]
    float* sXT = smem + K * 64;      // [K][128] swizzled
    float* sAS = sXT + K * 128;      // [64] if ATT
    float* sAD = sAS + 64;
    __shared__ unsigned s_mx[2];

    if (NC != 64) {
        for (int i = threadIdx.x; i < K * 64; i += 128) sW[i] = 0.f;
    }
    if (ATT) {
        if (threadIdx.x < 2) s_mx[threadIdx.x] = 0u;
        for (int i = threadIdx.x; i < 64; i += 128) {
            sAS[i] = (i < NC) ? attS[i] : 0.f;
            sAD[i] = (i < NC) ? attD[i] : 0.f;
        }
    }
    if (NC != 64) __syncthreads();
    for (int i = threadIdx.x; i < K * NC; i += 128)
        sW[(i / NC) * 64 + (i % NC)] = Wg[i];

    const int base = blockIdx.x * 128;
    constexpr int K4 = K / 4;
    for (int u = threadIdx.x; u < 128 * K4; u += 128) {
        int kq  = u & (K4 - 1);
        int row = u / K4;
        int gr = base + row;
        float4 v = make_float4(0.f, 0.f, 0.f, 0.f);
        if (gr < NNODES) v = *(const float4*)&X[(size_t)gr * K + kq * 4];
        int rsw = row ^ ((kq & 7) * 4);
        sXT[(kq * 4 + 0) * 128 + rsw] = v.x;
        sXT[(kq * 4 + 1) * 128 + rsw] = v.y;
        sXT[(kq * 4 + 2) * 128 + rsw] = v.z;
        sXT[(kq * 4 + 3) * 128 + rsw] = v.w;
    }
    __syncthreads();

    const int cg = threadIdx.x & 7;     // 8 cols: cg*8 .. +7
    const int rg = threadIdx.x >> 3;    // 8 rows: rg*8 .. +7

    unsigned long long acc[8][4];
#pragma unroll
    for (int r = 0; r < 8; r++)
#pragma unroll
        for (int cp = 0; cp < 4; cp++) acc[r][cp] = 0ull;

#pragma unroll 4
    for (int k = 0; k < K; k++) {
        int s4 = ((k >> 2) & 7) * 4;
        int a0 = (rg * 8) ^ s4;
        float4 xa = *(const float4*)&sXT[k * 128 + a0];
        float4 xb = *(const float4*)&sXT[k * 128 + (a0 ^ 4)];
        double2 wva = *(const double2*)&sW[k * 64 + cg * 8];
        double2 wvb = *(const double2*)&sW[k * 64 + cg * 8 + 4];
        unsigned long long w01 = __double_as_longlong(wva.x);
        unsigned long long w23 = __double_as_longlong(wva.y);
        unsigned long long w45 = __double_as_longlong(wvb.x);
        unsigned long long w67 = __double_as_longlong(wvb.y);
        unsigned long long xd;
        DUP2(xd, xa.x);
        FMA2(acc[0][0], xd, w01); FMA2(acc[0][1], xd, w23);
        FMA2(acc[0][2], xd, w45); FMA2(acc[0][3], xd, w67);
        DUP2(xd, xa.y);
        FMA2(acc[1][0], xd, w01); FMA2(acc[1][1], xd, w23);
        FMA2(acc[1][2], xd, w45); FMA2(acc[1][3], xd, w67);
        DUP2(xd, xa.z);
        FMA2(acc[2][0], xd, w01); FMA2(acc[2][1], xd, w23);
        FMA2(acc[2][2], xd, w45); FMA2(acc[2][3], xd, w67);
        DUP2(xd, xa.w);
        FMA2(acc[3][0], xd, w01); FMA2(acc[3][1], xd, w23);
        FMA2(acc[3][2], xd, w45); FMA2(acc[3][3], xd, w67);
        DUP2(xd, xb.x);
        FMA2(acc[4][0], xd, w01); FMA2(acc[4][1], xd, w23);
        FMA2(acc[4][2], xd, w45); FMA2(acc[4][3], xd, w67);
        DUP2(xd, xb.y);
        FMA2(acc[5][0], xd, w01); FMA2(acc[5][1], xd, w23);
        FMA2(acc[5][2], xd, w45); FMA2(acc[5][3], xd, w67);
        DUP2(xd, xb.z);
        FMA2(acc[6][0], xd, w01); FMA2(acc[6][1], xd, w23);
        FMA2(acc[6][2], xd, w45); FMA2(acc[6][3], xd, w67);
        DUP2(xd, xb.w);
        FMA2(acc[7][0], xd, w01); FMA2(acc[7][1], xd, w23);
        FMA2(acc[7][2], xd, w45); FMA2(acc[7][3], xd, w67);
    }

    const int c0 = cg * 8;
    float4 ba = make_float4(0.f, 0.f, 0.f, 0.f), bb = ba;
    if (BIAS && c0 < NC) {
        ba = *(const float4*)&bias[c0];
        bb = *(const float4*)&bias[c0 + 4];
    }
    float4 sa1, sa2, sd1, sd2;
    if (ATT) {
        sa1 = *(const float4*)&sAS[c0]; sa2 = *(const float4*)&sAS[c0 + 4];
        sd1 = *(const float4*)&sAD[c0]; sd2 = *(const float4*)&sAD[c0 + 4];
    }

#pragma unroll
    for (int r = 0; r < 8; r++) {
        int gr = base + rg * 8 + r;
        float4 oa, ob;
        oa.x = f2lo(acc[r][0]); oa.y = f2hi(acc[r][0]);
        oa.z = f2lo(acc[r][1]); oa.w = f2hi(acc[r][1]);
        ob.x = f2lo(acc[r][2]); ob.y = f2hi(acc[r][2]);
        ob.z = f2lo(acc[r][3]); ob.w = f2hi(acc[r][3]);

        if (BIAS && c0 < NC) {
            oa.x += ba.x; oa.y += ba.y; oa.z += ba.z; oa.w += ba.w;
            ob.x += bb.x; ob.y += bb.y; ob.z += bb.z; ob.w += bb.w;
        }
        if (RELU) {
            oa.x = fmaxf(oa.x, 0.f); oa.y = fmaxf(oa.y, 0.f);
            oa.z = fmaxf(oa.z, 0.f); oa.w = fmaxf(oa.w, 0.f);
            ob.x = fmaxf(ob.x, 0.f); ob.y = fmaxf(ob.y, 0.f);
            ob.z = fmaxf(ob.z, 0.f); ob.w = fmaxf(ob.w, 0.f);
        }

        if (ATT) {
            float ps = oa.x * sa1.x + oa.y * sa1.y + oa.z * sa1.z + oa.w * sa1.w
                     + ob.x * sa2.x + ob.y * sa2.y + ob.z * sa2.z + ob.w * sa2.w;
            float pd = oa.x * sd1.x + oa.y * sd1.y + oa.z * sd1.z + oa.w * sd1.w
                     + ob.x * sd2.x + ob.y * sd2.y + ob.z * sd2.z + ob.w * sd2.w;
#pragma unroll
            for (int off = 4; off; off >>= 1) {
                ps += __shfl_xor_sync(0xffffffffu, ps, off, 8);
                pd += __shfl_xor_sync(0xffffffffu, pd, off, 8);
            }
            if (cg == 0 && gr < NNODES) {
                g_as[gr] = ps; g_ad[gr] = pd;
                atomicMax(&s_mx[0], fenc(ps));
                atomicMax(&s_mx[1], fenc(pd));
            }
        }

        if (LSM) {
            float lm = -1e30f;
            if (c0 < NC) {
                lm = fmaxf(fmaxf(fmaxf(oa.x, oa.y), fmaxf(oa.z, oa.w)),
                           fmaxf(fmaxf(ob.x, ob.y), fmaxf(ob.z, ob.w)));
            }
#pragma unroll
            for (int off = 4; off; off >>= 1)
                lm = fmaxf(lm, __shfl_xor_sync(0xffffffffu, lm, off, 8));
            float le = 0.f;
            if (c0 < NC) {
                le = __expf(oa.x - lm) + __expf(oa.y - lm) + __expf(oa.z - lm) + __expf(oa.w - lm)
                   + __expf(ob.x - lm) + __expf(ob.y - lm) + __expf(ob.z - lm) + __expf(ob.w - lm);
            }
#pragma unroll
            for (int off = 4; off; off >>= 1)
                le += __shfl_xor_sync(0xffffffffu, le, off, 8);
            float lse = lm + __logf(le);
            if (c0 < NC && gr < NNODES) {
                oa.x -= lse; oa.y -= lse; oa.z -= lse; oa.w -= lse;
                ob.x -= lse; ob.y -= lse; ob.z -= lse; ob.w -= lse;
                *(float4*)&out[(size_t)gr * NC + c0] = oa;
                *(float4*)&out[(size_t)gr * NC + c0 + 4] = ob;
            }
        } else if (c0 < NC && gr < NNODES) {
            *(float4*)&out[(size_t)gr * NC + c0] = oa;
            *(float4*)&out[(size_t)gr * NC + c0 + 4] = ob;
        }
    }

    if (ATT) {
        __syncthreads();
        if (threadIdx.x == 0) {
            atomicMax(&g_mxu[slot * 2],     s_mx[0]);
            atomicMax(&g_mxu[slot * 2 + 1], s_mx[1]);
        }
    }
}

// ------------------------------ GAT aggregate -------------------------------
__global__ void k_agg(const float* __restrict__ h, float* __restrict__ out,
                      int slot) {
    int gw = (blockIdx.x * blockDim.x + threadIdx.x) >> 5;
    int lane = threadIdx.x & 31;
    if (gw >= NNODES) return;
    int beg = g_off[gw], end = g_off[gw + 1];
    float adv = g_ad[gw];
    float m = lrelu(fdec(g_mxu[slot * 2]) + fdec(g_mxu[slot * 2 + 1]));

    float wself = __expf(lrelu(g_as[gw] + adv) - m);
    float dsum = (lane == 0) ? wself : 0.f;

    unsigned long long acc;
    {
        unsigned long long hv = *(const unsigned long long*)&h[(size_t)gw * 64 + lane * 2];
        unsigned long long wd; DUP2(wd, wself);
        acc = 0ull;
        FMA2(acc, wd, hv);
    }

    for (int chunk = beg; chunk < end; chunk += 32) {
        int idx = chunk + lane;
        int s = 0; float w = 0.f;
        if (idx < end) {
            s = g_csr_src[idx];
            w = __expf(lrelu(g_as[s] + adv) - m);
        }
        dsum += w;
        int cnt = end - chunk;
        if (cnt >= 32) {
#pragma unroll 4
            for (int j = 0; j < 32; j++) {
                int   sj = __shfl_sync(0xffffffffu, s, j);
                float wj = __shfl_sync(0xffffffffu, w, j);
                unsigned long long hv = *(const unsigned long long*)&h[(size_t)sj * 64 + lane * 2];
                unsigned long long wd; DUP2(wd, wj);
                FMA2(acc, wd, hv);
            }
        } else {
            for (int j = 0; j < cnt; j++) {
                int   sj = __shfl_sync(0xffffffffu, s, j);
                float wj = __shfl_sync(0xffffffffu, w, j);
                unsigned long long hv = *(const unsigned long long*)&h[(size_t)sj * 64 + lane * 2];
                unsigned long long wd; DUP2(wd, wj);
                FMA2(acc, wd, hv);
            }
        }
    }
#pragma unroll
    for (int o = 16; o; o >>= 1) dsum += __shfl_xor_sync(0xffffffffu, dsum, o);

    float inv = 1.0f / (dsum + 1e-16f);
    float2 ov = make_float2(f2lo(acc) * inv, f2hi(acc) * inv);
    *(float2*)&out[(size_t)gw * 64 + lane * 2] = ov;
}

// ------------------------------ launch --------------------------------------
extern "C" void kernel_launch(void* const* d_in, const int* in_sizes, int n_in,
                              void* d_out, int out_size) {
    const float* x    = (const float*)d_in[0];
    const void*  ei   = d_in[1];
    const float* W1   = (const float*)d_in[2];
    const float* b1   = (const float*)d_in[3];
    const float* Wc0  = (const float*)d_in[4];
    const float* as0  = (const float*)d_in[5];
    const float* ad0  = (const float*)d_in[6];
    const float* bi0  = (const float*)d_in[7];
    const float* Wc1  = (const float*)d_in[8];
    const float* as1  = (const float*)d_in[9];
    const float* ad1  = (const float*)d_in[10];
    const float* bi1  = (const float*)d_in[11];
    const float* W2   = (const float*)d_in[12];
    const float* b2   = (const float*)d_in[13];
    float*       outp = (float*)d_out;

    int E = in_sizes[1] / 2;
    if (E > EMAX) E = EMAX;

    float *pA = nullptr, *pB = nullptr, *pWv = nullptr, *pWf = nullptr, *pBf = nullptr;
    cudaGetSymbolAddress((void**)&pA, g_bufA);
    cudaGetSymbolAddress((void**)&pB, g_bufB);
    cudaGetSymbolAddress((void**)&pWv, g_wvec);
    cudaGetSymbolAddress((void**)&pWf, g_Wfin);
    cudaGetSymbolAddress((void**)&pBf, g_bfin);

    size_t sm1 = (size_t)(FIN * 64 + FIN * 128 + 128) * 4;      // 98816 -> 2 CTAs/SM
    size_t smA = (size_t)(HID * 64 + HID * 128 + 128) * 4;      // 49664 -> 4 CTAs/SM
    size_t sm3 = (size_t)(HID * 64 + HID * 128) * 4;            // 49152 -> 4 CTAs/SM
    cudaFuncSetAttribute(k_gemm<FIN, HID, true, true, true, false>,
                         cudaFuncAttributeMaxDynamicSharedMemorySize, (int)sm1);
    cudaFuncSetAttribute(k_gemm<HID, HID, true, true, true, false>,
                         cudaFuncAttributeMaxDynamicSharedMemorySize, (int)smA);
    cudaFuncSetAttribute(k_gemm<HID, NCLS, false, true, false, true>,
                         cudaFuncAttributeMaxDynamicSharedMemorySize, (int)sm3);

    static cudaStream_t s_side = nullptr;
    static cudaEvent_t  ev_fork = nullptr, ev_cvt = nullptr, ev_join = nullptr;
    if (!s_side) {
        cudaStreamCreateWithFlags(&s_side, cudaStreamNonBlocking);
        cudaEventCreateWithFlags(&ev_fork, cudaEventDisableTiming);
        cudaEventCreateWithFlags(&ev_cvt,  cudaEventDisableTiming);
        cudaEventCreateWithFlags(&ev_join, cudaEventDisableTiming);
    }

    const int NTILES = (NNODES + 127) / 128;

    // fork: side stream owns the CSR chain. Enqueue order is chosen so the
    // profiler's captured launch (enqueue index 3) is gemm1.
    cudaEventRecord(ev_fork, 0);
    cudaStreamWaitEvent(s_side, ev_fork, 0);
    // 0, 1: first half of the side chain
    k_init<<<(NNODES + 255) / 256, 256, 0, s_side>>>((const int*)ei, in_sizes[1]);
    k_convert_hist<<<(E + 255) / 256, 256, 0, s_side>>>(ei, E);
    // 2: main precompute (independent of side)
    k_pre<<<21, 128>>>(Wc0, as0, ad0, Wc1, as1, ad1, W2, bi1, b2);
    // 3 (PROFILED): h = relu(x@W1+b1) + collapsed layer-0 att dots
    k_gemm<FIN, HID, true, true, true, false><<<NTILES, 128, sm1>>>(
        x, W1, b1, pWv, pWv + 64, pA, 0);
    // 4, 5: rest of the side chain (runs concurrent with gemm1)
    k_scan<<<(NNODES + 1023) / 1024, 1024, 0, s_side>>>();
    k_scatter<<<(E + 255) / 256, 256, 0, s_side>>>(E);
    cudaEventRecord(ev_join, s_side);

    // join CSR, aggregate raw h
    cudaStreamWaitEvent(0, ev_join, 0);
    k_agg<<<(NNODES * 32 + 255) / 256, 256>>>(pA, pB, 0);
    // h1 = relu(g0@Wc0+bias0) + collapsed layer-1 att dots
    k_gemm<HID, HID, true, true, true, false><<<NTILES, 128, smA>>>(
        pB, Wc0, bi0, pWv + 128, pWv + 192, pA, 1);
    k_agg<<<(NNODES * 32 + 255) / 256, 256>>>(pA, pB, 1);
    // out = log_softmax(g1 @ (Wc1 W2) + (bias1 W2 + b2))
    k_gemm<HID, NCLS, false, true, false, true><<<NTILES, 128, sm3>>>(
        pB, pWf, pBf, nullptr, nullptr, outp, -1);
}

// round 16
// speedup vs baseline: 1.0677x; 1.0677x over previous
#include <cuda_runtime.h>
#include <cstdint>

#define NNODES 100000
#define EMAX   1700000
#define HID    64
#define FIN    128
#define NCLS   40

// ------------------------------ device scratch ------------------------------
__device__ float g_bufA[NNODES * HID];
__device__ float g_bufB[NNODES * HID];
__device__ float g_as[NNODES];
__device__ float g_ad[NNODES];
__device__ int   g_deg[NNODES];
__device__ int   g_off[NNODES + 1];
__device__ int   g_pos[NNODES];
__device__ int   g_csr_src[EMAX];
__device__ int   g_esrc[EMAX];
__device__ int   g_edst[EMAX];
__device__ int   g_bsum[128];
__device__ volatile int g_flag[128];
__device__ int   g_idx32;
__device__ unsigned g_mxu[4];
__device__ float g_wvec[256];
__device__ float g_Wfin[HID * NCLS];   // Wc1 @ W2
__device__ float g_bfin[NCLS];         // bias1 @ W2 + b2

__device__ __forceinline__ float lrelu(float x) { return x > 0.f ? x : 0.2f * x; }

__device__ __forceinline__ unsigned fenc(float f) {
    unsigned u = __float_as_uint(f);
    return (u & 0x80000000u) ? ~u : (u | 0x80000000u);
}
__device__ __forceinline__ float fdec(unsigned k) {
    return (k & 0x80000000u) ? __uint_as_float(k & 0x7fffffffu)
                             : __uint_as_float(~k);
}

#define FMA2(d, a, b) asm("fma.rn.f32x2 %0, %1, %2, %0;" : "+l"(d) : "l"(a), "l"(b))
#define DUP2(d, f)    asm("mov.b64 %0, {%1, %1};" : "=l"(d) : "f"(f))

__device__ __forceinline__ float f2lo(unsigned long long v) {
    return __uint_as_float((unsigned)(v & 0xffffffffu));
}
__device__ __forceinline__ float f2hi(unsigned long long v) {
    return __uint_as_float((unsigned)(v >> 32));
}

__device__ __forceinline__ unsigned f2tf(float f) {
    unsigned r;
    asm("cvt.rna.tf32.f32 %0, %1;" : "=r"(r) : "f"(f));
    return r;
}

#define MMA8(d, a, b0, b1) \
    asm volatile("mma.sync.aligned.m16n8k8.row.col.f32.tf32.tf32.f32 " \
                 "{%0,%1,%2,%3},{%4,%5,%6,%7},{%8,%9},{%0,%1,%2,%3};" \
                 : "+f"((d)[0]), "+f"((d)[1]), "+f"((d)[2]), "+f"((d)[3]) \
                 : "r"((a)[0]), "r"((a)[1]), "r"((a)[2]), "r"((a)[3]), \
                   "r"(b0), "r"(b1))

// ------------- init (side stream): zero deg/flags, detect dtype -------------
__global__ void k_init(const int* __restrict__ w, int nwords) {
    __shared__ int nz;
    int i = blockIdx.x * blockDim.x + threadIdx.x;
    if (i < NNODES) g_deg[i] = 0;
    if (i < 128) g_flag[i] = 0;
    if (blockIdx.x == 0) {
        if (threadIdx.x == 0) nz = 0;
        __syncthreads();
        int n = nwords < 4096 ? nwords : 4096;
        int found = 0;
        for (int j = 2 * threadIdx.x + 1; j < n; j += 2 * blockDim.x)
            if (w[j] != 0) found = 1;
        if (found) atomicExch(&nz, 1);
        __syncthreads();
        if (threadIdx.x == 0) g_idx32 = nz;
    }
}

// ------------- precompute (main stream, parallel): collapsed weights --------
__global__ void k_pre(const float* __restrict__ Wc0, const float* __restrict__ aS0,
                      const float* __restrict__ aD0,
                      const float* __restrict__ Wc1, const float* __restrict__ aS1,
                      const float* __restrict__ aD1,
                      const float* __restrict__ W2, const float* __restrict__ bi1,
                      const float* __restrict__ b2) {
    int t = threadIdx.x;
    if (blockIdx.x == 0) {
        if (t < 4) g_mxu[t] = 0u;
        if (t >= 128) return;
        if (t < 64) {
            float s0 = 0.f, d0 = 0.f, s1 = 0.f, d1 = 0.f;
#pragma unroll 8
            for (int k = 0; k < 64; k++) {
                float w0 = Wc0[t * 64 + k];
                float w1 = Wc1[t * 64 + k];
                s0 += w0 * aS0[k]; d0 += w0 * aD0[k];
                s1 += w1 * aS1[k]; d1 += w1 * aD1[k];
            }
            g_wvec[t] = s0; g_wvec[64 + t] = d0;
            g_wvec[128 + t] = s1; g_wvec[192 + t] = d1;
        } else if (t - 64 < NCLS) {
            int j = t - 64;
            float s = b2[j];
#pragma unroll 8
            for (int k = 0; k < 64; k++) s += bi1[k] * W2[k * NCLS + j];
            g_bfin[j] = s;
        }
    } else {
        int idx = (blockIdx.x - 1) * 128 + t;
        if (idx < HID * NCLS) {
            int i = idx / NCLS, j = idx % NCLS;
            float s = 0.f;
#pragma unroll 8
            for (int k = 0; k < 64; k++) s += Wc1[i * 64 + k] * W2[k * NCLS + j];
            g_Wfin[idx] = s;
        }
    }
}

__global__ void k_convert_hist(const void* __restrict__ ei, int E) {
    int e = blockIdx.x * blockDim.x + threadIdx.x;
    if (e >= E) return;
    int s, d;
    if (g_idx32) {
        const int* p = (const int*)ei;
        s = p[e]; d = p[E + e];
    } else {
        const long long* p = (const long long*)ei;
        s = (int)p[e]; d = (int)p[E + e];
    }
    g_esrc[e] = s;
    g_edst[e] = d;
    atomicAdd(&g_deg[d], 1);
}

// ---------------- single-kernel scan (all 98 blocks resident) ---------------
__global__ void k_scan() {
    __shared__ int sh[1024];
    __shared__ int s_off;
    int bid = blockIdx.x;
    int tid = threadIdx.x;
    int i = bid * 1024 + tid;
    int v = (i < NNODES) ? g_deg[i] : 0;
    sh[tid] = v;
    if (tid == 0) s_off = 0;
    __syncthreads();
    for (int o = 1; o < 1024; o <<= 1) {
        int t = 0;
        if (tid >= o) t = sh[tid - o];
        __syncthreads();
        sh[tid] += t;
        __syncthreads();
    }
    if (tid == 1023) {
        g_bsum[bid] = sh[1023];
        __threadfence();
        g_flag[bid] = 1;
    }
    if (tid < bid) {
        while (g_flag[tid] == 0) { }
        atomicAdd(&s_off, g_bsum[tid]);
    }
    __syncthreads();
    if (i < NNODES) {
        int incl = sh[tid] + s_off;
        int excl = incl - v;
        g_off[i] = excl;
        g_pos[i] = excl;
        if (i == NNODES - 1) g_off[NNODES] = incl;
    }
}

__global__ void k_scatter(int E) {
    int e = blockIdx.x * blockDim.x + threadIdx.x;
    if (e < E) {
        int d = g_edst[e];
        int p = atomicAdd(&g_pos[d], 1);
        g_csr_src[p] = g_esrc[e];
    }
}

// ------------------------- GEMM (tensor core, tf32 split) -------------------
// 128-thread CTA (4 warps), 128-row x 64-col tile. mma.sync m16n8k8 tf32 with
// 3-product hi/lo split (error ~2^-22). Per warp: 32 rows x 64 cols.
// sX: fp32 [128][KC+4] (pad -> conflict-free A-frag LDS).
// sWhi/sWlo: tf32-split W, [K][72] (stride 72 -> conflict-free B-frag LDS).
template <int K, int KC, int NC, bool ATT, bool BIAS, bool RELU, bool LSM>
__global__ void k_gemm(const float* __restrict__ X, const float* __restrict__ Wg,
                       const float* __restrict__ bias,
                       const float* __restrict__ attS, const float* __restrict__ attD,
                       float* __restrict__ out, int slot) {
    constexpr int KCp = KC + 4;
    extern __shared__ float smem[];
    float* sX   = smem;                       // [128][KCp]
    float* sWhi = smem + 128 * KCp;           // [K][72]
    float* sWlo = sWhi + K * 72;              // [K][72]
    float* sAS  = sWlo + K * 72;              // [64]
    float* sAD  = sAS + 64;                   // [64]
    __shared__ unsigned s_mx[2];

    const int tid = threadIdx.x;
    const int lane = tid & 31;
    const int g  = lane >> 2;       // 0..7
    const int tg = lane & 3;        // 0..3
    const int wr = (tid >> 5) * 32; // warp row offset
    const int base = blockIdx.x * 128;

    // ---- stage W (tf32 split) ----
    if (NC != 64) {
        for (int i = tid; i < K * 72; i += 128) { sWhi[i] = 0.f; sWlo[i] = 0.f; }
    }
    if (ATT) {
        if (tid < 2) s_mx[tid] = 0u;
        for (int i = tid; i < 64; i += 128) {
            sAS[i] = (i < NC) ? attS[i] : 0.f;
            sAD[i] = (i < NC) ? attD[i] : 0.f;
        }
    }
    if (NC != 64) __syncthreads();
    for (int i = tid; i < K * NC; i += 128) {
        int k = i / NC, n = i % NC;
        float w = Wg[i];
        unsigned h = f2tf(w);
        float hf = __uint_as_float(h);
        sWhi[k * 72 + n] = hf;
        sWlo[k * 72 + n] = __uint_as_float(f2tf(w - hf));
    }

    float acc[2][8][4];
#pragma unroll
    for (int mt = 0; mt < 2; mt++)
#pragma unroll
        for (int nt = 0; nt < 8; nt++)
#pragma unroll
            for (int c = 0; c < 4; c++) acc[mt][nt][c] = 0.f;

    for (int kc = 0; kc < K; kc += KC) {
        __syncthreads();   // W/AS staged (1st) / prior sX reads done (later)
        for (int u = tid; u < 128 * (KC / 4); u += 128) {
            int kq  = u & (KC / 4 - 1);
            int row = u / (KC / 4);
            int gr = base + row;
            float4 v = make_float4(0.f, 0.f, 0.f, 0.f);
            if (gr < NNODES) v = *(const float4*)&X[(size_t)gr * K + kc + kq * 4];
            *(float4*)&sX[row * KCp + kq * 4] = v;
        }
        __syncthreads();

#pragma unroll 2
        for (int s = 0; s < KC / 8; s++) {
            const int k0l = s * 8;
            const int kg = kc + k0l;
            unsigned ahi[2][4], alo[2][4];
#pragma unroll
            for (int mt = 0; mt < 2; mt++) {
                int rb = wr + mt * 16 + g;
                float a0 = sX[rb * KCp + k0l + tg];
                float a1 = sX[(rb + 8) * KCp + k0l + tg];
                float a2 = sX[rb * KCp + k0l + tg + 4];
                float a3 = sX[(rb + 8) * KCp + k0l + tg + 4];
                unsigned h;
                h = f2tf(a0); ahi[mt][0] = h; alo[mt][0] = f2tf(a0 - __uint_as_float(h));
                h = f2tf(a1); ahi[mt][1] = h; alo[mt][1] = f2tf(a1 - __uint_as_float(h));
                h = f2tf(a2); ahi[mt][2] = h; alo[mt][2] = f2tf(a2 - __uint_as_float(h));
                h = f2tf(a3); ahi[mt][3] = h; alo[mt][3] = f2tf(a3 - __uint_as_float(h));
            }
#pragma unroll
            for (int nt = 0; nt < 8; nt++) {
                int cb = nt * 8 + g;
                unsigned bh0 = __float_as_uint(sWhi[(kg + tg) * 72 + cb]);
                unsigned bh1 = __float_as_uint(sWhi[(kg + tg + 4) * 72 + cb]);
                unsigned bl0 = __float_as_uint(sWlo[(kg + tg) * 72 + cb]);
                unsigned bl1 = __float_as_uint(sWlo[(kg + tg + 4) * 72 + cb]);
                MMA8(acc[0][nt], ahi[0], bh0, bh1);
                MMA8(acc[0][nt], ahi[0], bl0, bl1);
                MMA8(acc[0][nt], alo[0], bh0, bh1);
                MMA8(acc[1][nt], ahi[1], bh0, bh1);
                MMA8(acc[1][nt], ahi[1], bl0, bl1);
                MMA8(acc[1][nt], alo[1], bh0, bh1);
            }
        }
    }

    // ---- epilogue: bias -> relu -> att dots -> store/LSM ----
    float bb0[8], bb1[8];
    float as0v[8], as1v[8], ad0v[8], ad1v[8];
#pragma unroll
    for (int nt = 0; nt < 8; nt++) {
        int col = nt * 8 + 2 * tg;
        if (BIAS && col < NC) { bb0[nt] = bias[col]; bb1[nt] = bias[col + 1]; }
        else { bb0[nt] = 0.f; bb1[nt] = 0.f; }
        if (ATT) {
            as0v[nt] = sAS[col]; as1v[nt] = sAS[col + 1];
            ad0v[nt] = sAD[col]; ad1v[nt] = sAD[col + 1];
        }
    }

#pragma unroll
    for (int mt = 0; mt < 2; mt++) {
#pragma unroll
        for (int half = 0; half < 2; half++) {
            int row = base + wr + mt * 16 + g + half * 8;
            float o0[8], o1[8];
#pragma unroll
            for (int nt = 0; nt < 8; nt++) {
                o0[nt] = acc[mt][nt][half * 2];
                o1[nt] = acc[mt][nt][half * 2 + 1];
            }
            if (BIAS) {
#pragma unroll
                for (int nt = 0; nt < 8; nt++) { o0[nt] += bb0[nt]; o1[nt] += bb1[nt]; }
            }
            if (RELU) {
#pragma unroll
                for (int nt = 0; nt < 8; nt++) {
                    o0[nt] = fmaxf(o0[nt], 0.f); o1[nt] = fmaxf(o1[nt], 0.f);
                }
            }
            if (ATT) {
                float ps = 0.f, pd = 0.f;
#pragma unroll
                for (int nt = 0; nt < 8; nt++) {
                    ps += o0[nt] * as0v[nt] + o1[nt] * as1v[nt];
                    pd += o0[nt] * ad0v[nt] + o1[nt] * ad1v[nt];
                }
                ps += __shfl_xor_sync(0xffffffffu, ps, 1, 4);
                ps += __shfl_xor_sync(0xffffffffu, ps, 2, 4);
                pd += __shfl_xor_sync(0xffffffffu, pd, 1, 4);
                pd += __shfl_xor_sync(0xffffffffu, pd, 2, 4);
                if (tg == 0 && row < NNODES) {
                    g_as[row] = ps; g_ad[row] = pd;
                    atomicMax(&s_mx[0], fenc(ps));
                    atomicMax(&s_mx[1], fenc(pd));
                }
            }
            if (LSM) {
                float lm = -1e30f;
#pragma unroll
                for (int nt = 0; nt < 8; nt++) {
                    int col = nt * 8 + 2 * tg;
                    if (col < NC) lm = fmaxf(lm, fmaxf(o0[nt], o1[nt]));
                }
                lm = fmaxf(lm, __shfl_xor_sync(0xffffffffu, lm, 1, 4));
                lm = fmaxf(lm, __shfl_xor_sync(0xffffffffu, lm, 2, 4));
                float le = 0.f;
#pragma unroll
                for (int nt = 0; nt < 8; nt++) {
                    int col = nt * 8 + 2 * tg;
                    if (col < NC) le += __expf(o0[nt] - lm) + __expf(o1[nt] - lm);
                }
                le += __shfl_xor_sync(0xffffffffu, le, 1, 4);
                le += __shfl_xor_sync(0xffffffffu, le, 2, 4);
                float lse = lm + __logf(le);
                if (row < NNODES) {
#pragma unroll
                    for (int nt = 0; nt < 8; nt++) {
                        int col = nt * 8 + 2 * tg;
                        if (col < NC)
                            *(float2*)&out[(size_t)row * NC + col] =
                                make_float2(o0[nt] - lse, o1[nt] - lse);
                    }
                }
            } else if (row < NNODES) {
#pragma unroll
                for (int nt = 0; nt < 8; nt++) {
                    int col = nt * 8 + 2 * tg;
                    if (col < NC)
                        *(float2*)&out[(size_t)row * NC + col] =
                            make_float2(o0[nt], o1[nt]);
                }
            }
        }
    }

    if (ATT) {
        __syncthreads();
        if (tid == 0) {
            atomicMax(&g_mxu[slot * 2],     s_mx[0]);
            atomicMax(&g_mxu[slot * 2 + 1], s_mx[1]);
        }
    }
}

// ------------------------------ GAT aggregate -------------------------------
__global__ void k_agg(const float* __restrict__ h, float* __restrict__ out,
                      int slot) {
    int gw = (blockIdx.x * blockDim.x + threadIdx.x) >> 5;
    int lane = threadIdx.x & 31;
    if (gw >= NNODES) return;
    int beg = g_off[gw], end = g_off[gw + 1];
    float adv = g_ad[gw];
    float m = lrelu(fdec(g_mxu[slot * 2]) + fdec(g_mxu[slot * 2 + 1]));

    float wself = __expf(lrelu(g_as[gw] + adv) - m);
    float dsum = (lane == 0) ? wself : 0.f;

    unsigned long long acc;
    {
        unsigned long long hv = *(const unsigned long long*)&h[(size_t)gw * 64 + lane * 2];
        unsigned long long wd; DUP2(wd, wself);
        acc = 0ull;
        FMA2(acc, wd, hv);
    }

    for (int chunk = beg; chunk < end; chunk += 32) {
        int idx = chunk + lane;
        int s = 0; float w = 0.f;
        if (idx < end) {
            s = g_csr_src[idx];
            w = __expf(lrelu(g_as[s] + adv) - m);
        }
        dsum += w;
        int cnt = end - chunk;
        if (cnt >= 32) {
#pragma unroll 4
            for (int j = 0; j < 32; j++) {
                int   sj = __shfl_sync(0xffffffffu, s, j);
                float wj = __shfl_sync(0xffffffffu, w, j);
                unsigned long long hv = *(const unsigned long long*)&h[(size_t)sj * 64 + lane * 2];
                unsigned long long wd; DUP2(wd, wj);
                FMA2(acc, wd, hv);
            }
        } else {
            for (int j = 0; j < cnt; j++) {
                int   sj = __shfl_sync(0xffffffffu, s, j);
                float wj = __shfl_sync(0xffffffffu, w, j);
                unsigned long long hv = *(const unsigned long long*)&h[(size_t)sj * 64 + lane * 2];
                unsigned long long wd; DUP2(wd, wj);
                FMA2(acc, wd, hv);
            }
        }
    }
#pragma unroll
    for (int o = 16; o; o >>= 1) dsum += __shfl_xor_sync(0xffffffffu, dsum, o);

    float inv = 1.0f / (dsum + 1e-16f);
    float2 ov = make_float2(f2lo(acc) * inv, f2hi(acc) * inv);
    *(float2*)&out[(size_t)gw * 64 + lane * 2] = ov;
}

// ------------------------------ launch --------------------------------------
extern "C" void kernel_launch(void* const* d_in, const int* in_sizes, int n_in,
                              void* d_out, int out_size) {
    const float* x    = (const float*)d_in[0];
    const void*  ei   = d_in[1];
    const float* W1   = (const float*)d_in[2];
    const float* b1   = (const float*)d_in[3];
    const float* Wc0  = (const float*)d_in[4];
    const float* as0  = (const float*)d_in[5];
    const float* ad0  = (const float*)d_in[6];
    const float* bi0  = (const float*)d_in[7];
    const float* Wc1  = (const float*)d_in[8];
    const float* as1  = (const float*)d_in[9];
    const float* ad1  = (const float*)d_in[10];
    const float* bi1  = (const float*)d_in[11];
    const float* W2   = (const float*)d_in[12];
    const float* b2   = (const float*)d_in[13];
    float*       outp = (float*)d_out;

    int E = in_sizes[1] / 2;
    if (E > EMAX) E = EMAX;

    float *pA = nullptr, *pB = nullptr, *pWv = nullptr, *pWf = nullptr, *pBf = nullptr;
    cudaGetSymbolAddress((void**)&pA, g_bufA);
    cudaGetSymbolAddress((void**)&pB, g_bufB);
    cudaGetSymbolAddress((void**)&pWv, g_wvec);
    cudaGetSymbolAddress((void**)&pWf, g_Wfin);
    cudaGetSymbolAddress((void**)&pBf, g_bfin);

    // smem: (128*(KC+4) + 2*K*72 + 128) * 4
    size_t sm1 = (size_t)(128 * 68 + 2 * FIN * 72 + 128) * 4;   // 109056 -> 2 CTAs/SM
    size_t smA = (size_t)(128 * 68 + 2 * HID * 72 + 128) * 4;   // 72192  -> 3 CTAs/SM
    cudaFuncSetAttribute(k_gemm<FIN, 64, HID, true, true, true, false>,
                         cudaFuncAttributeMaxDynamicSharedMemorySize, (int)sm1);
    cudaFuncSetAttribute(k_gemm<HID, 64, HID, true, true, true, false>,
                         cudaFuncAttributeMaxDynamicSharedMemorySize, (int)smA);
    cudaFuncSetAttribute(k_gemm<HID, 64, NCLS, false, true, false, true>,
                         cudaFuncAttributeMaxDynamicSharedMemorySize, (int)smA);

    static cudaStream_t s_side = nullptr;
    static cudaEvent_t  ev_fork = nullptr, ev_join = nullptr;
    if (!s_side) {
        cudaStreamCreateWithFlags(&s_side, cudaStreamNonBlocking);
        cudaEventCreateWithFlags(&ev_fork, cudaEventDisableTiming);
        cudaEventCreateWithFlags(&ev_join, cudaEventDisableTiming);
    }

    const int NTILES = (NNODES + 127) / 128;

    // fork: side stream owns the CSR chain; gemm1 at enqueue index 3 (profiled)
    cudaEventRecord(ev_fork, 0);
    cudaStreamWaitEvent(s_side, ev_fork, 0);
    // 0, 1
    k_init<<<(NNODES + 255) / 256, 256, 0, s_side>>>((const int*)ei, in_sizes[1]);
    k_convert_hist<<<(E + 255) / 256, 256, 0, s_side>>>(ei, E);
    // 2
    k_pre<<<21, 128>>>(Wc0, as0, ad0, Wc1, as1, ad1, W2, bi1, b2);
    // 3 (PROFILED): h = relu(x@W1+b1) + layer-0 att dots (tensor core)
    k_gemm<FIN, 64, HID, true, true, true, false><<<NTILES, 128, sm1>>>(
        x, W1, b1, pWv, pWv + 64, pA, 0);
    // 4, 5
    k_scan<<<(NNODES + 1023) / 1024, 1024, 0, s_side>>>();
    k_scatter<<<(E + 255) / 256, 256, 0, s_side>>>(E);
    cudaEventRecord(ev_join, s_side);

    // join CSR, aggregate raw h
    cudaStreamWaitEvent(0, ev_join, 0);
    k_agg<<<(NNODES * 32 + 255) / 256, 256>>>(pA, pB, 0);
    // h1 = relu(g0@Wc0+bias0) + layer-1 att dots
    k_gemm<HID, 64, HID, true, true, true, false><<<NTILES, 128, smA>>>(
        pB, Wc0, bi0, pWv + 128, pWv + 192, pA, 1);
    k_agg<<<(NNODES * 32 + 255) / 256, 256>>>(pA, pB, 1);
    // out = log_softmax(g1 @ (Wc1 W2) + (bias1 W2 + b2))
    k_gemm<HID, 64, NCLS, false, true, false, true><<<NTILES, 128, smA>>>(
        pB, pWf, pBf, nullptr, nullptr, outp, -1);
}

// round 17
// speedup vs baseline: 1.1427x; 1.0702x over previous
#include <cuda_runtime.h>
#include <cstdint>

#define NNODES 100000
#define EMAX   1700000
#define HID    64
#define FIN    128
#define NCLS   40

// ------------------------------ device scratch ------------------------------
__device__ float g_bufA[NNODES * HID];
__device__ float g_bufB[NNODES * HID];
__device__ float g_as[NNODES];
__device__ float g_ad[NNODES];
__device__ int   g_deg[NNODES];
__device__ int   g_off[NNODES + 1];
__device__ int   g_pos[NNODES];
__device__ int   g_csr_src[EMAX];
__device__ int   g_esrc[EMAX];
__device__ int   g_edst[EMAX];
__device__ int   g_bsum[128];
__device__ volatile int g_flag[128];
__device__ int   g_idx32;
__device__ unsigned g_mxu[4];
__device__ float g_wvec[256];
__device__ float g_Wfin[HID * NCLS];   // Wc1 @ W2
__device__ float g_bfin[NCLS];         // bias1 @ W2 + b2

__device__ __forceinline__ float lrelu(float x) { return x > 0.f ? x : 0.2f * x; }

__device__ __forceinline__ unsigned fenc(float f) {
    unsigned u = __float_as_uint(f);
    return (u & 0x80000000u) ? ~u : (u | 0x80000000u);
}
__device__ __forceinline__ float fdec(unsigned k) {
    return (k & 0x80000000u) ? __uint_as_float(k & 0x7fffffffu)
                             : __uint_as_float(~k);
}

#define FMA2(d, a, b) asm("fma.rn.f32x2 %0, %1, %2, %0;" : "+l"(d) : "l"(a), "l"(b))
#define DUP2(d, f)    asm("mov.b64 %0, {%1, %1};" : "=l"(d) : "f"(f))

__device__ __forceinline__ float f2lo(unsigned long long v) {
    return __uint_as_float((unsigned)(v & 0xffffffffu));
}
__device__ __forceinline__ float f2hi(unsigned long long v) {
    return __uint_as_float((unsigned)(v >> 32));
}

__device__ __forceinline__ unsigned f2tf(float f) {
    unsigned r;
    asm("cvt.rna.tf32.f32 %0, %1;" : "=r"(r) : "f"(f));
    return r;
}

#define MMA8(d, a, b0, b1) \
    asm volatile("mma.sync.aligned.m16n8k8.row.col.f32.tf32.tf32.f32 " \
                 "{%0,%1,%2,%3},{%4,%5,%6,%7},{%8,%9},{%0,%1,%2,%3};" \
                 : "+f"((d)[0]), "+f"((d)[1]), "+f"((d)[2]), "+f"((d)[3]) \
                 : "r"((a)[0]), "r"((a)[1]), "r"((a)[2]), "r"((a)[3]), \
                   "r"(b0), "r"(b1))

// ------------- init (side stream): zero deg/flags, detect dtype -------------
__global__ void k_init(const int* __restrict__ w, int nwords) {
    __shared__ int nz;
    int i = blockIdx.x * blockDim.x + threadIdx.x;
    if (i < NNODES) g_deg[i] = 0;
    if (i < 128) g_flag[i] = 0;
    if (blockIdx.x == 0) {
        if (threadIdx.x == 0) nz = 0;
        __syncthreads();
        int n = nwords < 4096 ? nwords : 4096;
        int found = 0;
        for (int j = 2 * threadIdx.x + 1; j < n; j += 2 * blockDim.x)
            if (w[j] != 0) found = 1;
        if (found) atomicExch(&nz, 1);
        __syncthreads();
        if (threadIdx.x == 0) g_idx32 = nz;
    }
}

// ------------- precompute (main stream, parallel): collapsed weights --------
__global__ void k_pre(const float* __restrict__ Wc0, const float* __restrict__ aS0,
                      const float* __restrict__ aD0,
                      const float* __restrict__ Wc1, const float* __restrict__ aS1,
                      const float* __restrict__ aD1,
                      const float* __restrict__ W2, const float* __restrict__ bi1,
                      const float* __restrict__ b2) {
    int t = threadIdx.x;
    if (blockIdx.x == 0) {
        if (t < 4) g_mxu[t] = 0u;
        if (t >= 128) return;
        if (t < 64) {
            float s0 = 0.f, d0 = 0.f, s1 = 0.f, d1 = 0.f;
#pragma unroll 8
            for (int k = 0; k < 64; k++) {
                float w0 = Wc0[t * 64 + k];
                float w1 = Wc1[t * 64 + k];
                s0 += w0 * aS0[k]; d0 += w0 * aD0[k];
                s1 += w1 * aS1[k]; d1 += w1 * aD1[k];
            }
            g_wvec[t] = s0; g_wvec[64 + t] = d0;
            g_wvec[128 + t] = s1; g_wvec[192 + t] = d1;
        } else if (t - 64 < NCLS) {
            int j = t - 64;
            float s = b2[j];
#pragma unroll 8
            for (int k = 0; k < 64; k++) s += bi1[k] * W2[k * NCLS + j];
            g_bfin[j] = s;
        }
    } else {
        int idx = (blockIdx.x - 1) * 128 + t;
        if (idx < HID * NCLS) {
            int i = idx / NCLS, j = idx % NCLS;
            float s = 0.f;
#pragma unroll 8
            for (int k = 0; k < 64; k++) s += Wc1[i * 64 + k] * W2[k * NCLS + j];
            g_Wfin[idx] = s;
        }
    }
}

__global__ void k_convert_hist(const void* __restrict__ ei, int E) {
    int e = blockIdx.x * blockDim.x + threadIdx.x;
    if (e >= E) return;
    int s, d;
    if (g_idx32) {
        const int* p = (const int*)ei;
        s = p[e]; d = p[E + e];
    } else {
        const long long* p = (const long long*)ei;
        s = (int)p[e]; d = (int)p[E + e];
    }
    g_esrc[e] = s;
    g_edst[e] = d;
    atomicAdd(&g_deg[d], 1);
}

// ---------------- single-kernel scan (all 98 blocks resident) ---------------
__global__ void k_scan() {
    __shared__ int sh[1024];
    __shared__ int s_off;
    int bid = blockIdx.x;
    int tid = threadIdx.x;
    int i = bid * 1024 + tid;
    int v = (i < NNODES) ? g_deg[i] : 0;
    sh[tid] = v;
    if (tid == 0) s_off = 0;
    __syncthreads();
    for (int o = 1; o < 1024; o <<= 1) {
        int t = 0;
        if (tid >= o) t = sh[tid - o];
        __syncthreads();
        sh[tid] += t;
        __syncthreads();
    }
    if (tid == 1023) {
        g_bsum[bid] = sh[1023];
        __threadfence();
        g_flag[bid] = 1;
    }
    if (tid < bid) {
        while (g_flag[tid] == 0) { }
        atomicAdd(&s_off, g_bsum[tid]);
    }
    __syncthreads();
    if (i < NNODES) {
        int incl = sh[tid] + s_off;
        int excl = incl - v;
        g_off[i] = excl;
        g_pos[i] = excl;
        if (i == NNODES - 1) g_off[NNODES] = incl;
    }
}

__global__ void k_scatter(int E) {
    int e = blockIdx.x * blockDim.x + threadIdx.x;
    if (e < E) {
        int d = g_edst[e];
        int p = atomicAdd(&g_pos[d], 1);
        g_csr_src[p] = g_esrc[e];
    }
}

// ------------------------- GEMM (tensor core, tf32 split) -------------------
// 256-thread CTA (8 warps), 128-row x 64-col tile; each warp: 16 rows x 64 cols.
// mma.sync m16n8k8 tf32 with 3-product hi/lo split (error ~2^-22).
// sX: fp32 [128][KC+4]; sWhi/sWlo: tf32-split W [K][72].
template <int K, int KC, int NC, bool ATT, bool BIAS, bool RELU, bool LSM>
__global__ void __launch_bounds__(256, 2)
k_gemm(const float* __restrict__ X, const float* __restrict__ Wg,
       const float* __restrict__ bias,
       const float* __restrict__ attS, const float* __restrict__ attD,
       float* __restrict__ out, int slot) {
    constexpr int KCp = KC + 4;
    extern __shared__ float smem[];
    float* sX   = smem;                       // [128][KCp]
    float* sWhi = smem + 128 * KCp;           // [K][72]
    float* sWlo = sWhi + K * 72;              // [K][72]
    float* sAS  = sWlo + K * 72;              // [64]
    float* sAD  = sAS + 64;                   // [64]
    __shared__ unsigned s_mx[2];

    const int tid = threadIdx.x;
    const int lane = tid & 31;
    const int g  = lane >> 2;       // 0..7
    const int tg = lane & 3;        // 0..3
    const int wr = (tid >> 5) * 16; // warp row offset (8 warps x 16 rows)
    const int base = blockIdx.x * 128;

    // ---- stage W (tf32 split) ----
    if (NC != 64) {
        for (int i = tid; i < K * 72; i += 256) { sWhi[i] = 0.f; sWlo[i] = 0.f; }
    }
    if (ATT) {
        if (tid < 2) s_mx[tid] = 0u;
        for (int i = tid; i < 64; i += 256) {
            sAS[i] = (i < NC) ? attS[i] : 0.f;
            sAD[i] = (i < NC) ? attD[i] : 0.f;
        }
    }
    if (NC != 64) __syncthreads();
    for (int i = tid; i < K * NC; i += 256) {
        int k = i / NC, n = i % NC;
        float w = Wg[i];
        unsigned h = f2tf(w);
        float hf = __uint_as_float(h);
        sWhi[k * 72 + n] = hf;
        sWlo[k * 72 + n] = __uint_as_float(f2tf(w - hf));
    }

    float acc[8][4];
#pragma unroll
    for (int nt = 0; nt < 8; nt++)
#pragma unroll
        for (int c = 0; c < 4; c++) acc[nt][c] = 0.f;

    for (int kc = 0; kc < K; kc += KC) {
        __syncthreads();   // W/AS staged (1st) / prior sX reads done (later)
        for (int u = tid; u < 128 * (KC / 4); u += 256) {
            int kq  = u & (KC / 4 - 1);
            int row = u / (KC / 4);
            int gr = base + row;
            float4 v = make_float4(0.f, 0.f, 0.f, 0.f);
            if (gr < NNODES) v = *(const float4*)&X[(size_t)gr * K + kc + kq * 4];
            *(float4*)&sX[row * KCp + kq * 4] = v;
        }
        __syncthreads();

#pragma unroll 2
        for (int s = 0; s < KC / 8; s++) {
            const int k0l = s * 8;
            const int kg = kc + k0l;
            unsigned ahi[4], alo[4];
            {
                int rb = wr + g;
                float a0 = sX[rb * KCp + k0l + tg];
                float a1 = sX[(rb + 8) * KCp + k0l + tg];
                float a2 = sX[rb * KCp + k0l + tg + 4];
                float a3 = sX[(rb + 8) * KCp + k0l + tg + 4];
                unsigned h;
                h = f2tf(a0); ahi[0] = h; alo[0] = f2tf(a0 - __uint_as_float(h));
                h = f2tf(a1); ahi[1] = h; alo[1] = f2tf(a1 - __uint_as_float(h));
                h = f2tf(a2); ahi[2] = h; alo[2] = f2tf(a2 - __uint_as_float(h));
                h = f2tf(a3); ahi[3] = h; alo[3] = f2tf(a3 - __uint_as_float(h));
            }
#pragma unroll
            for (int nt = 0; nt < 8; nt++) {
                int cb = nt * 8 + g;
                unsigned bh0 = __float_as_uint(sWhi[(kg + tg) * 72 + cb]);
                unsigned bh1 = __float_as_uint(sWhi[(kg + tg + 4) * 72 + cb]);
                unsigned bl0 = __float_as_uint(sWlo[(kg + tg) * 72 + cb]);
                unsigned bl1 = __float_as_uint(sWlo[(kg + tg + 4) * 72 + cb]);
                MMA8(acc[nt], ahi, bh0, bh1);
                MMA8(acc[nt], ahi, bl0, bl1);
                MMA8(acc[nt], alo, bh0, bh1);
            }
        }
    }

    // ---- epilogue: bias -> relu -> att dots -> store/LSM ----
    float bb0[8], bb1[8];
    float as0v[8], as1v[8], ad0v[8], ad1v[8];
#pragma unroll
    for (int nt = 0; nt < 8; nt++) {
        int col = nt * 8 + 2 * tg;
        if (BIAS && col < NC) { bb0[nt] = bias[col]; bb1[nt] = bias[col + 1]; }
        else { bb0[nt] = 0.f; bb1[nt] = 0.f; }
        if (ATT) {
            as0v[nt] = sAS[col]; as1v[nt] = sAS[col + 1];
            ad0v[nt] = sAD[col]; ad1v[nt] = sAD[col + 1];
        }
    }

#pragma unroll
    for (int half = 0; half < 2; half++) {
        int row = base + wr + g + half * 8;
        float o0[8], o1[8];
#pragma unroll
        for (int nt = 0; nt < 8; nt++) {
            o0[nt] = acc[nt][half * 2];
            o1[nt] = acc[nt][half * 2 + 1];
        }
        if (BIAS) {
#pragma unroll
            for (int nt = 0; nt < 8; nt++) { o0[nt] += bb0[nt]; o1[nt] += bb1[nt]; }
        }
        if (RELU) {
#pragma unroll
            for (int nt = 0; nt < 8; nt++) {
                o0[nt] = fmaxf(o0[nt], 0.f); o1[nt] = fmaxf(o1[nt], 0.f);
            }
        }
        if (ATT) {
            float ps = 0.f, pd = 0.f;
#pragma unroll
            for (int nt = 0; nt < 8; nt++) {
                ps += o0[nt] * as0v[nt] + o1[nt] * as1v[nt];
                pd += o0[nt] * ad0v[nt] + o1[nt] * ad1v[nt];
            }
            ps += __shfl_xor_sync(0xffffffffu, ps, 1, 4);
            ps += __shfl_xor_sync(0xffffffffu, ps, 2, 4);
            pd += __shfl_xor_sync(0xffffffffu, pd, 1, 4);
            pd += __shfl_xor_sync(0xffffffffu, pd, 2, 4);
            if (tg == 0 && row < NNODES) {
                g_as[row] = ps; g_ad[row] = pd;
                atomicMax(&s_mx[0], fenc(ps));
                atomicMax(&s_mx[1], fenc(pd));
            }
        }
        if (LSM) {
            float lm = -1e30f;
#pragma unroll
            for (int nt = 0; nt < 8; nt++) {
                int col = nt * 8 + 2 * tg;
                if (col < NC) lm = fmaxf(lm, fmaxf(o0[nt], o1[nt]));
            }
            lm = fmaxf(lm, __shfl_xor_sync(0xffffffffu, lm, 1, 4));
            lm = fmaxf(lm, __shfl_xor_sync(0xffffffffu, lm, 2, 4));
            float le = 0.f;
#pragma unroll
            for (int nt = 0; nt < 8; nt++) {
                int col = nt * 8 + 2 * tg;
                if (col < NC) le += __expf(o0[nt] - lm) + __expf(o1[nt] - lm);
            }
            le += __shfl_xor_sync(0xffffffffu, le, 1, 4);
            le += __shfl_xor_sync(0xffffffffu, le, 2, 4);
            float lse = lm + __logf(le);
            if (row < NNODES) {
#pragma unroll
                for (int nt = 0; nt < 8; nt++) {
                    int col = nt * 8 + 2 * tg;
                    if (col < NC)
                        *(float2*)&out[(size_t)row * NC + col] =
                            make_float2(o0[nt] - lse, o1[nt] - lse);
                }
            }
        } else if (row < NNODES) {
#pragma unroll
            for (int nt = 0; nt < 8; nt++) {
                int col = nt * 8 + 2 * tg;
                if (col < NC)
                    *(float2*)&out[(size_t)row * NC + col] =
                        make_float2(o0[nt], o1[nt]);
            }
        }
    }

    if (ATT) {
        __syncthreads();
        if (tid == 0) {
            atomicMax(&g_mxu[slot * 2],     s_mx[0]);
            atomicMax(&g_mxu[slot * 2 + 1], s_mx[1]);
        }
    }
}

// ------------------------------ GAT aggregate -------------------------------
__global__ void k_agg(const float* __restrict__ h, float* __restrict__ out,
                      int slot) {
    int gw = (blockIdx.x * blockDim.x + threadIdx.x) >> 5;
    int lane = threadIdx.x & 31;
    if (gw >= NNODES) return;
    int beg = g_off[gw], end = g_off[gw + 1];
    float adv = g_ad[gw];
    float m = lrelu(fdec(g_mxu[slot * 2]) + fdec(g_mxu[slot * 2 + 1]));

    float wself = __expf(lrelu(g_as[gw] + adv) - m);
    float dsum = (lane == 0) ? wself : 0.f;

    unsigned long long acc;
    {
        unsigned long long hv = *(const unsigned long long*)&h[(size_t)gw * 64 + lane * 2];
        unsigned long long wd; DUP2(wd, wself);
        acc = 0ull;
        FMA2(acc, wd, hv);
    }

    for (int chunk = beg; chunk < end; chunk += 32) {
        int idx = chunk + lane;
        int s = 0; float w = 0.f;
        if (idx < end) {
            s = g_csr_src[idx];
            w = __expf(lrelu(g_as[s] + adv) - m);
        }
        dsum += w;
        int cnt = end - chunk;
        if (cnt >= 32) {
#pragma unroll 4
            for (int j = 0; j < 32; j++) {
                int   sj = __shfl_sync(0xffffffffu, s, j);
                float wj = __shfl_sync(0xffffffffu, w, j);
                unsigned long long hv = *(const unsigned long long*)&h[(size_t)sj * 64 + lane * 2];
                unsigned long long wd; DUP2(wd, wj);
                FMA2(acc, wd, hv);
            }
        } else {
            for (int j = 0; j < cnt; j++) {
                int   sj = __shfl_sync(0xffffffffu, s, j);
                float wj = __shfl_sync(0xffffffffu, w, j);
                unsigned long long hv = *(const unsigned long long*)&h[(size_t)sj * 64 + lane * 2];
                unsigned long long wd; DUP2(wd, wj);
                FMA2(acc, wd, hv);
            }
        }
    }
#pragma unroll
    for (int o = 16; o; o >>= 1) dsum += __shfl_xor_sync(0xffffffffu, dsum, o);

    float inv = 1.0f / (dsum + 1e-16f);
    float2 ov = make_float2(f2lo(acc) * inv, f2hi(acc) * inv);
    *(float2*)&out[(size_t)gw * 64 + lane * 2] = ov;
}

// ------------------------------ launch --------------------------------------
extern "C" void kernel_launch(void* const* d_in, const int* in_sizes, int n_in,
                              void* d_out, int out_size) {
    const float* x    = (const float*)d_in[0];
    const void*  ei   = d_in[1];
    const float* W1   = (const float*)d_in[2];
    const float* b1   = (const float*)d_in[3];
    const float* Wc0  = (const float*)d_in[4];
    const float* as0  = (const float*)d_in[5];
    const float* ad0  = (const float*)d_in[6];
    const float* bi0  = (const float*)d_in[7];
    const float* Wc1  = (const float*)d_in[8];
    const float* as1  = (const float*)d_in[9];
    const float* ad1  = (const float*)d_in[10];
    const float* bi1  = (const float*)d_in[11];
    const float* W2   = (const float*)d_in[12];
    const float* b2   = (const float*)d_in[13];
    float*       outp = (float*)d_out;

    int E = in_sizes[1] / 2;
    if (E > EMAX) E = EMAX;

    float *pA = nullptr, *pB = nullptr, *pWv = nullptr, *pWf = nullptr, *pBf = nullptr;
    cudaGetSymbolAddress((void**)&pA, g_bufA);
    cudaGetSymbolAddress((void**)&pB, g_bufB);
    cudaGetSymbolAddress((void**)&pWv, g_wvec);
    cudaGetSymbolAddress((void**)&pWf, g_Wfin);
    cudaGetSymbolAddress((void**)&pBf, g_bfin);

    // smem: (128*(KC+4) + 2*K*72 + 128) * 4
    size_t sm1 = (size_t)(128 * 68 + 2 * FIN * 72 + 128) * 4;   // 109056 -> 2 CTAs/SM
    size_t smA = (size_t)(128 * 68 + 2 * HID * 72 + 128) * 4;   // 72192
    cudaFuncSetAttribute(k_gemm<FIN, 64, HID, true, true, true, false>,
                         cudaFuncAttributeMaxDynamicSharedMemorySize, (int)sm1);
    cudaFuncSetAttribute(k_gemm<HID, 64, HID, true, true, true, false>,
                         cudaFuncAttributeMaxDynamicSharedMemorySize, (int)smA);
    cudaFuncSetAttribute(k_gemm<HID, 64, NCLS, false, true, false, true>,
                         cudaFuncAttributeMaxDynamicSharedMemorySize, (int)smA);

    static cudaStream_t s_side = nullptr;
    static cudaEvent_t  ev_fork = nullptr, ev_join = nullptr;
    if (!s_side) {
        cudaStreamCreateWithFlags(&s_side, cudaStreamNonBlocking);
        cudaEventCreateWithFlags(&ev_fork, cudaEventDisableTiming);
        cudaEventCreateWithFlags(&ev_join, cudaEventDisableTiming);
    }

    const int NTILES = (NNODES + 127) / 128;

    // fork: side stream owns the CSR chain; gemm1 at enqueue index 3 (profiled)
    cudaEventRecord(ev_fork, 0);
    cudaStreamWaitEvent(s_side, ev_fork, 0);
    // 0, 1
    k_init<<<(NNODES + 255) / 256, 256, 0, s_side>>>((const int*)ei, in_sizes[1]);
    k_convert_hist<<<(E + 255) / 256, 256, 0, s_side>>>(ei, E);
    // 2
    k_pre<<<21, 128>>>(Wc0, as0, ad0, Wc1, as1, ad1, W2, bi1, b2);
    // 3 (PROFILED): h = relu(x@W1+b1) + layer-0 att dots (tensor core)
    k_gemm<FIN, 64, HID, true, true, true, false><<<NTILES, 256, sm1>>>(
        x, W1, b1, pWv, pWv + 64, pA, 0);
    // 4, 5
    k_scan<<<(NNODES + 1023) / 1024, 1024, 0, s_side>>>();
    k_scatter<<<(E + 255) / 256, 256, 0, s_side>>>(E);
    cudaEventRecord(ev_join, s_side);

    // join CSR, aggregate raw h
    cudaStreamWaitEvent(0, ev_join, 0);
    k_agg<<<(NNODES * 32 + 255) / 256, 256>>>(pA, pB, 0);
    // h1 = relu(g0@Wc0+bias0) + layer-1 att dots
    k_gemm<HID, 64, HID, true, true, true, false><<<NTILES, 256, smA>>>(
        pB, Wc0, bi0, pWv + 128, pWv + 192, pA, 1);
    k_agg<<<(NNODES * 32 + 255) / 256, 256>>>(pA, pB, 1);
    // out = log_softmax(g1 @ (Wc1 W2) + (bias1 W2 + b2))
    k_gemm<HID, 64, NCLS, false, true, false, true><<<NTILES, 256, smA>>>(
        pB, pWf, pBf, nullptr, nullptr, outp, -1);
}